// round 14
// baseline (speedup 1.0000x reference)
#include <cuda_runtime.h>
#include <cuda_bf16.h>
#include <cstdint>

// Problem shapes (fixed by dataset)
#define KK 2048   // batch/k dim
#define MM 512    // feature dim m
#define NN 64     // target dim n
#define EPSV 1e-8f
#define LMAX 32

// ---------------- scratch (static device globals; no allocation) ----------------
__device__ float g_S[KK * MM];     // logits x @ w_att
__device__ float g_soft[KK * MM];  // fallback scores_soft sink
__device__ float g_hard[MM * NN];  // fallback scores_hard sink

// ---------------- tf32 helpers ----------------------------------------------
__device__ __forceinline__ uint32_t f2tf32(float f) {
    uint32_t r;
    asm("cvt.rna.tf32.f32 %0, %1;" : "=r"(r) : "f"(f));
    return r;
}
__device__ __forceinline__ void split_tf32(float f, uint32_t& hi, uint32_t& lo) {
    hi = f2tf32(f);
    lo = f2tf32(f - __uint_as_float(hi));
}
__device__ __forceinline__ void mma_tf32(float& c0, float& c1, float& c2, float& c3,
                                         uint32_t a0, uint32_t a1, uint32_t a2, uint32_t a3,
                                         uint32_t b0, uint32_t b1) {
    asm volatile(
        "mma.sync.aligned.m16n8k8.row.col.f32.tf32.tf32.f32 "
        "{%0,%1,%2,%3}, {%4,%5,%6,%7}, {%8,%9}, {%0,%1,%2,%3};"
        : "+f"(c0), "+f"(c1), "+f"(c2), "+f"(c3)
        : "r"(a0), "r"(a1), "r"(a2), "r"(a3), "r"(b0), "r"(b1));
}

// ---------------- Kernel 1: 2-split TF32 GEMM, pre-split smem ---------------
// S[KK,MM] = x[KK,512] @ w_att[512,MM].  Block tile 64x64, BK=16.
// hi/lo tf32 split happens ONCE per value during the global->smem stage;
// the inner loop is pure LDS + HMMA.
#define BM 64
#define BN 64
#define BK 16
#define AS_STRIDE 20   // banks (m*20 + k) % 32 all-distinct for frag pattern
#define BS_STRIDE 72   // banks (k*72 + n) % 32 all-distinct for frag pattern
__global__ __launch_bounds__(256) void gemm_kernel(const float* __restrict__ A,
                                                   const float* __restrict__ B) {
    __shared__ uint32_t Ah[BM][AS_STRIDE], Al[BM][AS_STRIDE];
    __shared__ uint32_t Bh[BK][BS_STRIDE], Bl[BK][BS_STRIDE];

    const int t    = threadIdx.x;
    const int w    = t >> 5;
    const int lane = t & 31;
    const int gid  = lane >> 2;   // 0..7
    const int tig  = lane & 3;    // 0..3
    const int wm   = (w >> 1) * 16;
    const int wn   = (w & 1) * 32;
    const int bm   = blockIdx.y * BM;
    const int bn   = blockIdx.x * BN;

    // global-load mappings (one float4 each per tile)
    const int arow = t >> 2;           // 0..63
    const int ac4  = (t & 3) << 2;     // 0,4,8,12
    const int brow = t >> 4;           // 0..15 (k)
    const int bc4  = (t & 15) << 2;    // 0..60 (n)

    float acc[4][4];
#pragma unroll
    for (int i = 0; i < 4; i++)
#pragma unroll
        for (int j = 0; j < 4; j++) acc[i][j] = 0.f;

    // prefetch tile 0
    float4 av = *(const float4*)&A[(size_t)(bm + arow) * MM + ac4];
    float4 bv = *(const float4*)&B[(size_t)brow * MM + bn + bc4];

    for (int kt = 0; kt < MM; kt += BK) {
        // split + commit prefetched tile to smem (each value split once)
        {
            uint32_t h, l;
            split_tf32(av.x, h, l); Ah[arow][ac4 + 0] = h; Al[arow][ac4 + 0] = l;
            split_tf32(av.y, h, l); Ah[arow][ac4 + 1] = h; Al[arow][ac4 + 1] = l;
            split_tf32(av.z, h, l); Ah[arow][ac4 + 2] = h; Al[arow][ac4 + 2] = l;
            split_tf32(av.w, h, l); Ah[arow][ac4 + 3] = h; Al[arow][ac4 + 3] = l;
            split_tf32(bv.x, h, l); Bh[brow][bc4 + 0] = h; Bl[brow][bc4 + 0] = l;
            split_tf32(bv.y, h, l); Bh[brow][bc4 + 1] = h; Bl[brow][bc4 + 1] = l;
            split_tf32(bv.z, h, l); Bh[brow][bc4 + 2] = h; Bl[brow][bc4 + 2] = l;
            split_tf32(bv.w, h, l); Bh[brow][bc4 + 3] = h; Bl[brow][bc4 + 3] = l;
        }
        __syncthreads();

        // prefetch next tile (LDG retires during compute)
        if (kt + BK < MM) {
            av = *(const float4*)&A[(size_t)(bm + arow) * MM + kt + BK + ac4];
            bv = *(const float4*)&B[(size_t)(kt + BK + brow) * MM + bn + bc4];
        }

#pragma unroll
        for (int ks = 0; ks < 2; ks++) {
            const int k0 = ks * 8;
            // A fragment (16x8): pure LDS
            uint32_t ah[4], al[4];
            ah[0] = Ah[wm + gid][k0 + tig];         al[0] = Al[wm + gid][k0 + tig];
            ah[1] = Ah[wm + gid + 8][k0 + tig];     al[1] = Al[wm + gid + 8][k0 + tig];
            ah[2] = Ah[wm + gid][k0 + tig + 4];     al[2] = Al[wm + gid][k0 + tig + 4];
            ah[3] = Ah[wm + gid + 8][k0 + tig + 4]; al[3] = Al[wm + gid + 8][k0 + tig + 4];

#pragma unroll
            for (int nt = 0; nt < 4; nt++) {
                const int n = wn + nt * 8 + gid;
                uint32_t bh0 = Bh[k0 + tig][n],     bl0 = Bl[k0 + tig][n];
                uint32_t bh1 = Bh[k0 + tig + 4][n], bl1 = Bl[k0 + tig + 4][n];

                // small cross terms first, then main term
                mma_tf32(acc[nt][0], acc[nt][1], acc[nt][2], acc[nt][3],
                         ah[0], ah[1], ah[2], ah[3], bl0, bl1);
                mma_tf32(acc[nt][0], acc[nt][1], acc[nt][2], acc[nt][3],
                         al[0], al[1], al[2], al[3], bh0, bh1);
                mma_tf32(acc[nt][0], acc[nt][1], acc[nt][2], acc[nt][3],
                         ah[0], ah[1], ah[2], ah[3], bh0, bh1);
            }
        }
        __syncthreads();
    }

    // store C: c0,c1 at (row, col), (row, col+1); c2,c3 at (row+8, col)
    const int row = bm + wm + gid;
#pragma unroll
    for (int nt = 0; nt < 4; nt++) {
        const int col = bn + wn + nt * 8 + tig * 2;
        *(float2*)&g_S[(size_t)row * MM + col] =
            make_float2(acc[nt][0], acc[nt][1]);
        *(float2*)&g_S[(size_t)(row + 8) * MM + col] =
            make_float2(acc[nt][2], acc[nt][3]);
    }
}

// ---------------- Kernel 2: softmax (R11-proven) + hard, block-specialized --
// Blocks 0..255: warp-per-row shuffle softmax (warp w owns k = bid*8 + w).
// Blocks 256..263: warp-per-column top-l + hard scores (R3-proven math).
__global__ __launch_bounds__(256) void soft_hard_kernel(float* __restrict__ dst,
                                                        const float* __restrict__ wb,
                                                        const int* __restrict__ lptr,
                                                        float* __restrict__ hard_dst) {
    const int bid  = blockIdx.x;
    const int w    = threadIdx.x >> 5;
    const int lane = threadIdx.x & 31;

    if (bid < 256) {
        // ---------------- softmax ----------------
        const int k = bid * 8 + w;
        const float* row = g_S + (size_t)k * MM;

        float4 v[4];
#pragma unroll
        for (int j = 0; j < 4; j++)
            v[j] = __ldg((const float4*)(row + (lane << 2) + 128 * j));

        float mx = -3.4e38f;
#pragma unroll
        for (int j = 0; j < 4; j++)
            mx = fmaxf(mx, fmaxf(fmaxf(v[j].x, v[j].y), fmaxf(v[j].z, v[j].w)));
#pragma unroll
        for (int off = 16; off > 0; off >>= 1)
            mx = fmaxf(mx, __shfl_xor_sync(0xffffffffu, mx, off));

        float sum = 0.f;
#pragma unroll
        for (int j = 0; j < 4; j++) {
            v[j].x = __expf(v[j].x - mx);
            v[j].y = __expf(v[j].y - mx);
            v[j].z = __expf(v[j].z - mx);
            v[j].w = __expf(v[j].w - mx);
            sum += v[j].x + v[j].y + v[j].z + v[j].w;
        }
#pragma unroll
        for (int off = 16; off > 0; off >>= 1)
            sum += __shfl_xor_sync(0xffffffffu, sum, off);
        float inv = 1.f / sum;

        float* drow = dst + (size_t)k * MM;
#pragma unroll
        for (int j = 0; j < 4; j++) {
            float4 s = make_float4(v[j].x * inv + EPSV, v[j].y * inv + EPSV,
                                   v[j].z * inv + EPSV, v[j].w * inv + EPSV);
            *(float4*)(drow + (lane << 2) + 128 * j) = s;
        }
    } else {
        // ---------------- hard scores: warp per n-column ----------------
        const int n = (bid - 256) * 8 + w;   // 0..63
        int l = lptr ? *lptr : 8;
        if (l < 1) l = 1;
        if (l > LMAX) l = LMAX;

        float v[16];
#pragma unroll
        for (int i = 0; i < 16; i++)
            v[i] = wb[(lane * 16 + i) * NN + n];

        float top[LMAX];
        for (int i = 0; i < l; i++) top[i] = -3.4e38f;
#pragma unroll
        for (int i = 0; i < 16; i++) {
            float x = v[i];
            if (x > top[l - 1]) {
                int j = l - 1;
                while (j > 0 && top[j - 1] < x) { top[j] = top[j - 1]; j--; }
                top[j] = x;
            }
        }

        int ptr = 0;
        float thr = -3.4e38f;
        for (int r = 0; r < l; r++) {
            float cand = (ptr < l) ? top[ptr] : -3.4e38f;
            float m = cand;
#pragma unroll
            for (int off = 16; off > 0; off >>= 1)
                m = fmaxf(m, __shfl_xor_sync(0xffffffffu, m, off));
            unsigned b = __ballot_sync(0xffffffffu, cand == m);
            int src = __ffs(b) - 1;
            if (lane == src) ptr++;
            thr = m;
        }

#pragma unroll
        for (int i = 0; i < 16; i++) {
            float sh = v[i] - thr + EPSV;
            sh = fminf(fmaxf(sh, -1.f), 1.f);
            float h = (sh + 1.f) * 0.5f;
            hard_dst[(lane * 16 + i) * NN + n] = h;
        }
    }
}

// ---------------- Kernel 3: epilogue (R5-proven EXACT) ----------------------
__global__ __launch_bounds__(256) void epilogue_kernel(const float* __restrict__ x,
                                                       const float* __restrict__ soft,
                                                       const float* __restrict__ hard,
                                                       float* __restrict__ out,
                                                       float* __restrict__ mw) {
    const int idx = blockIdx.x * blockDim.x + threadIdx.x;  // 0 .. KK*MM*16-1
    const int n4  = idx & 15;
    const int km  = idx >> 4;       // 0 .. KK*MM-1
    const int m   = km & (MM - 1);

    float ss = __ldg(&soft[km]);
    float xv = __ldg(&x[km]);
    float4 h = __ldg((const float4*)(hard + m * NN + (n4 << 2)));

    float4 mw4 = make_float4(h.x * ss, h.y * ss, h.z * ss, h.w * ss);
    float4 o4  = make_float4(mw4.x * xv, mw4.y * xv, mw4.z * xv, mw4.w * xv);

    size_t base = (size_t)km * NN + (n4 << 2);
    *(float4*)&out[base] = o4;
    if (mw) *(float4*)&mw[base] = mw4;
}

// ---------------- launch: 3 sequential kernels ------------------------------
extern "C" void kernel_launch(void* const* d_in, const int* in_sizes, int n_in,
                              void* d_out, int out_size) {
    const float* x     = (const float*)d_in[0];
    const float* w_att = (const float*)d_in[1];
    const float* w_b   = (const float*)d_in[2];
    const int*   lptr  = (n_in > 3) ? (const int*)d_in[3] : nullptr;

    const long SZ_OUT  = (long)KK * MM * NN;
    const long SZ_HARD = (long)MM * NN;
    const long SZ_SOFT = (long)KK * MM;

    float* out_ptr = (float*)d_out;
    float* hard_dst;
    float* soft_dst;
    float* mw_ptr = nullptr;
    if ((long)out_size >= SZ_OUT + SZ_HARD + SZ_SOFT + SZ_OUT) {
        hard_dst = out_ptr + SZ_OUT;
        soft_dst = hard_dst + SZ_HARD;
        mw_ptr   = soft_dst + SZ_SOFT;
    } else {
        float* dummy;
        cudaGetSymbolAddress((void**)&dummy, g_hard);
        hard_dst = dummy;
        cudaGetSymbolAddress((void**)&dummy, g_soft);
        soft_dst = dummy;
    }

    dim3 ggrid(MM / BN, KK / BM);
    gemm_kernel<<<ggrid, 256>>>(x, w_att);

    soft_hard_kernel<<<256 + 8, 256>>>(soft_dst, w_b, lptr, hard_dst);

    epilogue_kernel<<<(KK * MM * 16) / 256, 256>>>(x, soft_dst, hard_dst,
                                                   out_ptr, mw_ptr);
}

// round 15
// speedup vs baseline: 1.4698x; 1.4698x over previous
#include <cuda_runtime.h>
#include <cuda_bf16.h>

// Problem shapes (fixed by dataset)
#define KK 2048   // batch/k dim
#define MM 512    // feature dim m
#define NN 64     // target dim n
#define EPSV 1e-8f
#define LMAX 32

// ---------------- scratch (static device globals; no allocation) ----------------
__device__ float g_S[KK * MM];     // logits x @ w_att
__device__ float g_soft[KK * MM];  // fallback scores_soft sink
__device__ float g_hard[MM * NN];  // fallback scores_hard sink

// ---------------- Kernel 1: fp32 tiled GEMM, software-pipelined (R11-proven)
#define BM 64
#define BN 64
#define BK 16
__global__ __launch_bounds__(256) void gemm_kernel(const float* __restrict__ A,
                                                   const float* __restrict__ B) {
    __shared__ float As[BK][BM + 4];
    __shared__ float Bs[BK][BN];

    const int t  = threadIdx.x;
    const int tx = t & 15;
    const int ty = t >> 4;
    const int bm = blockIdx.y * BM;
    const int bn = blockIdx.x * BN;

    const int arow = t >> 2;
    const int ac4  = (t & 3) << 2;
    const int brow = t >> 4;
    const int bc4  = (t & 15) << 2;

    float acc[4][4];
#pragma unroll
    for (int i = 0; i < 4; i++)
#pragma unroll
        for (int j = 0; j < 4; j++) acc[i][j] = 0.f;

    // prefetch tile 0
    float4 av = *(const float4*)&A[(size_t)(bm + arow) * MM + ac4];
    float4 bv = *(const float4*)&B[(size_t)brow * MM + bn + bc4];

    for (int kt = 0; kt < MM; kt += BK) {
        // commit prefetched tile to smem
        As[ac4 + 0][arow] = av.x;
        As[ac4 + 1][arow] = av.y;
        As[ac4 + 2][arow] = av.z;
        As[ac4 + 3][arow] = av.w;
        *(float4*)&Bs[brow][bc4] = bv;
        __syncthreads();

        // prefetch next tile (LDG retires during compute)
        if (kt + BK < MM) {
            av = *(const float4*)&A[(size_t)(bm + arow) * MM + kt + BK + ac4];
            bv = *(const float4*)&B[(size_t)(kt + BK + brow) * MM + bn + bc4];
        }

#pragma unroll
        for (int kk = 0; kk < BK; kk++) {
            float4 a = *(const float4*)&As[kk][ty << 2];
            float4 b = *(const float4*)&Bs[kk][tx << 2];
            acc[0][0] += a.x * b.x; acc[0][1] += a.x * b.y; acc[0][2] += a.x * b.z; acc[0][3] += a.x * b.w;
            acc[1][0] += a.y * b.x; acc[1][1] += a.y * b.y; acc[1][2] += a.y * b.z; acc[1][3] += a.y * b.w;
            acc[2][0] += a.z * b.x; acc[2][1] += a.z * b.y; acc[2][2] += a.z * b.z; acc[2][3] += a.z * b.w;
            acc[3][0] += a.w * b.x; acc[3][1] += a.w * b.y; acc[3][2] += a.w * b.z; acc[3][3] += a.w * b.w;
        }
        __syncthreads();
    }

#pragma unroll
    for (int i = 0; i < 4; i++) {
        float4 v = make_float4(acc[i][0], acc[i][1], acc[i][2], acc[i][3]);
        *(float4*)&g_S[(size_t)(bm + (ty << 2) + i) * MM + bn + (tx << 2)] = v;
    }
}

// ---------------- Kernel 2: softmax (R11-proven) + hard, block-specialized --
// Blocks 0..255: warp-per-row shuffle softmax (warp w owns k = bid*8 + w).
// Blocks 256..263: warp-per-column top-l + hard scores (R3-proven math).
__global__ __launch_bounds__(256) void soft_hard_kernel(float* __restrict__ dst,
                                                        const float* __restrict__ wb,
                                                        const int* __restrict__ lptr,
                                                        float* __restrict__ hard_dst) {
    const int bid  = blockIdx.x;
    const int w    = threadIdx.x >> 5;
    const int lane = threadIdx.x & 31;

    if (bid < 256) {
        // ---------------- softmax ----------------
        const int k = bid * 8 + w;
        const float* row = g_S + (size_t)k * MM;

        float4 v[4];
#pragma unroll
        for (int j = 0; j < 4; j++)
            v[j] = __ldg((const float4*)(row + (lane << 2) + 128 * j));

        float mx = -3.4e38f;
#pragma unroll
        for (int j = 0; j < 4; j++)
            mx = fmaxf(mx, fmaxf(fmaxf(v[j].x, v[j].y), fmaxf(v[j].z, v[j].w)));
#pragma unroll
        for (int off = 16; off > 0; off >>= 1)
            mx = fmaxf(mx, __shfl_xor_sync(0xffffffffu, mx, off));

        float sum = 0.f;
#pragma unroll
        for (int j = 0; j < 4; j++) {
            v[j].x = __expf(v[j].x - mx);
            v[j].y = __expf(v[j].y - mx);
            v[j].z = __expf(v[j].z - mx);
            v[j].w = __expf(v[j].w - mx);
            sum += v[j].x + v[j].y + v[j].z + v[j].w;
        }
#pragma unroll
        for (int off = 16; off > 0; off >>= 1)
            sum += __shfl_xor_sync(0xffffffffu, sum, off);
        float inv = 1.f / sum;

        float* drow = dst + (size_t)k * MM;
#pragma unroll
        for (int j = 0; j < 4; j++) {
            float4 s = make_float4(v[j].x * inv + EPSV, v[j].y * inv + EPSV,
                                   v[j].z * inv + EPSV, v[j].w * inv + EPSV);
            *(float4*)(drow + (lane << 2) + 128 * j) = s;
        }
    } else {
        // ---------------- hard scores: warp per n-column ----------------
        const int n = (bid - 256) * 8 + w;   // 0..63
        int l = lptr ? *lptr : 8;
        if (l < 1) l = 1;
        if (l > LMAX) l = LMAX;

        float v[16];
#pragma unroll
        for (int i = 0; i < 16; i++)
            v[i] = wb[(lane * 16 + i) * NN + n];

        float top[LMAX];
        for (int i = 0; i < l; i++) top[i] = -3.4e38f;
#pragma unroll
        for (int i = 0; i < 16; i++) {
            float x = v[i];
            if (x > top[l - 1]) {
                int j = l - 1;
                while (j > 0 && top[j - 1] < x) { top[j] = top[j - 1]; j--; }
                top[j] = x;
            }
        }

        int ptr = 0;
        float thr = -3.4e38f;
        for (int r = 0; r < l; r++) {
            float cand = (ptr < l) ? top[ptr] : -3.4e38f;
            float m = cand;
#pragma unroll
            for (int off = 16; off > 0; off >>= 1)
                m = fmaxf(m, __shfl_xor_sync(0xffffffffu, m, off));
            unsigned b = __ballot_sync(0xffffffffu, cand == m);
            int src = __ffs(b) - 1;
            if (lane == src) ptr++;
            thr = m;
        }

#pragma unroll
        for (int i = 0; i < 16; i++) {
            float sh = v[i] - thr + EPSV;
            sh = fminf(fmaxf(sh, -1.f), 1.f);
            float h = (sh + 1.f) * 0.5f;
            hard_dst[(lane * 16 + i) * NN + n] = h;
        }
    }
}

// ---------------- Kernel 3: epilogue (R5-proven EXACT) ----------------------
// 16 threads per (k,m); each owns one float4 of n. Plain .wb stores.
__global__ __launch_bounds__(256) void epilogue_kernel(const float* __restrict__ x,
                                                       const float* __restrict__ soft,
                                                       const float* __restrict__ hard,
                                                       float* __restrict__ out,
                                                       float* __restrict__ mw) {
    const int idx = blockIdx.x * blockDim.x + threadIdx.x;  // 0 .. KK*MM*16-1
    const int n4  = idx & 15;
    const int km  = idx >> 4;       // 0 .. KK*MM-1
    const int m   = km & (MM - 1);

    float ss = __ldg(&soft[km]);
    float xv = __ldg(&x[km]);
    float4 h = __ldg((const float4*)(hard + m * NN + (n4 << 2)));

    float4 mw4 = make_float4(h.x * ss, h.y * ss, h.z * ss, h.w * ss);
    float4 o4  = make_float4(mw4.x * xv, mw4.y * xv, mw4.z * xv, mw4.w * xv);

    size_t base = (size_t)km * NN + (n4 << 2);
    *(float4*)&out[base] = o4;
    if (mw) *(float4*)&mw[base] = mw4;
}

// ---------------- launch: 3 sequential kernels ------------------------------
extern "C" void kernel_launch(void* const* d_in, const int* in_sizes, int n_in,
                              void* d_out, int out_size) {
    const float* x     = (const float*)d_in[0];
    const float* w_att = (const float*)d_in[1];
    const float* w_b   = (const float*)d_in[2];
    const int*   lptr  = (n_in > 3) ? (const int*)d_in[3] : nullptr;

    const long SZ_OUT  = (long)KK * MM * NN;
    const long SZ_HARD = (long)MM * NN;
    const long SZ_SOFT = (long)KK * MM;

    float* out_ptr = (float*)d_out;
    float* hard_dst;
    float* soft_dst;
    float* mw_ptr = nullptr;
    if ((long)out_size >= SZ_OUT + SZ_HARD + SZ_SOFT + SZ_OUT) {
        hard_dst = out_ptr + SZ_OUT;
        soft_dst = hard_dst + SZ_HARD;
        mw_ptr   = soft_dst + SZ_SOFT;
    } else {
        float* dummy;
        cudaGetSymbolAddress((void**)&dummy, g_hard);
        hard_dst = dummy;
        cudaGetSymbolAddress((void**)&dummy, g_soft);
        soft_dst = dummy;
    }

    dim3 ggrid(MM / BN, KK / BM);
    gemm_kernel<<<ggrid, 256>>>(x, w_att);

    soft_hard_kernel<<<256 + 8, 256>>>(soft_dst, w_b, lptr, hard_dst);

    epilogue_kernel<<<(KK * MM * 16) / 256, 256>>>(x, soft_dst, hard_dst,
                                                   out_ptr, mw_ptr);
}

// round 16
// speedup vs baseline: 1.4921x; 1.0152x over previous
#include <cuda_runtime.h>
#include <cuda_bf16.h>
#include <cstdint>

// Problem shapes (fixed by dataset)
#define KK 2048   // batch/k dim
#define MM 512    // feature dim m
#define NN 64     // target dim n
#define EPSV 1e-8f
#define LMAX 32

// ---------------- scratch (static device globals; no allocation) ----------------
__device__ float g_S[KK * MM];     // logits x @ w_att
__device__ float g_soft[KK * MM];  // fallback scores_soft sink
__device__ float g_hard[MM * NN];  // fallback scores_hard sink

// ---------------- Kernel 1: fp32 GEMM, software-pipelined, FFMA2 inner loop -
// R11-proven 64x64x16 geometry and load mappings; the 16 scalar FFMAs per
// kk-step are replaced by 8 packed fma.rn.f32x2 (sm_103a FFMA2), halving
// fma-pipe issue pressure at identical fp32 numerics.
#define BM 64
#define BN 64
#define BK 16
__global__ __launch_bounds__(256) void gemm_kernel(const float* __restrict__ A,
                                                   const float* __restrict__ B) {
    __shared__ float As[BK][BM + 4];
    __shared__ float Bs[BK][BN];

    const int t  = threadIdx.x;
    const int tx = t & 15;
    const int ty = t >> 4;
    const int bm = blockIdx.y * BM;
    const int bn = blockIdx.x * BN;

    const int arow = t >> 2;
    const int ac4  = (t & 3) << 2;
    const int brow = t >> 4;
    const int bc4  = (t & 15) << 2;

    // acc2[i][p]: packed pair (c[i][2p], c[i][2p+1]) — 16 fp32 in 8 regpairs
    uint64_t acc2[4][2];
#pragma unroll
    for (int i = 0; i < 4; i++) {
        acc2[i][0] = 0ull;
        acc2[i][1] = 0ull;
    }

    // prefetch tile 0
    float4 av = *(const float4*)&A[(size_t)(bm + arow) * MM + ac4];
    float4 bv = *(const float4*)&B[(size_t)brow * MM + bn + bc4];

    for (int kt = 0; kt < MM; kt += BK) {
        // commit prefetched tile to smem (A transposed)
        As[ac4 + 0][arow] = av.x;
        As[ac4 + 1][arow] = av.y;
        As[ac4 + 2][arow] = av.z;
        As[ac4 + 3][arow] = av.w;
        *(float4*)&Bs[brow][bc4] = bv;
        __syncthreads();

        // prefetch next tile (LDG retires during compute)
        if (kt + BK < MM) {
            av = *(const float4*)&A[(size_t)(bm + arow) * MM + kt + BK + ac4];
            bv = *(const float4*)&B[(size_t)(kt + BK + brow) * MM + bn + bc4];
        }

#pragma unroll
        for (int kk = 0; kk < BK; kk++) {
            float4 a = *(const float4*)&As[kk][ty << 2];
            // B quad read as two packed f32x2 operands (16B-aligned)
            ulonglong2 b2 = *(const ulonglong2*)&Bs[kk][tx << 2];

            uint64_t ap;
            asm("mov.b64 %0, {%1,%1};" : "=l"(ap) : "f"(a.x));
            asm("fma.rn.f32x2 %0, %1, %2, %0;" : "+l"(acc2[0][0]) : "l"(ap), "l"(b2.x));
            asm("fma.rn.f32x2 %0, %1, %2, %0;" : "+l"(acc2[0][1]) : "l"(ap), "l"(b2.y));
            asm("mov.b64 %0, {%1,%1};" : "=l"(ap) : "f"(a.y));
            asm("fma.rn.f32x2 %0, %1, %2, %0;" : "+l"(acc2[1][0]) : "l"(ap), "l"(b2.x));
            asm("fma.rn.f32x2 %0, %1, %2, %0;" : "+l"(acc2[1][1]) : "l"(ap), "l"(b2.y));
            asm("mov.b64 %0, {%1,%1};" : "=l"(ap) : "f"(a.z));
            asm("fma.rn.f32x2 %0, %1, %2, %0;" : "+l"(acc2[2][0]) : "l"(ap), "l"(b2.x));
            asm("fma.rn.f32x2 %0, %1, %2, %0;" : "+l"(acc2[2][1]) : "l"(ap), "l"(b2.y));
            asm("mov.b64 %0, {%1,%1};" : "=l"(ap) : "f"(a.w));
            asm("fma.rn.f32x2 %0, %1, %2, %0;" : "+l"(acc2[3][0]) : "l"(ap), "l"(b2.x));
            asm("fma.rn.f32x2 %0, %1, %2, %0;" : "+l"(acc2[3][1]) : "l"(ap), "l"(b2.y));
        }
        __syncthreads();
    }

#pragma unroll
    for (int i = 0; i < 4; i++) {
        uint32_t c0, c1, c2, c3;
        asm("mov.b64 {%0,%1}, %2;" : "=r"(c0), "=r"(c1) : "l"(acc2[i][0]));
        asm("mov.b64 {%0,%1}, %2;" : "=r"(c2), "=r"(c3) : "l"(acc2[i][1]));
        float4 v = make_float4(__uint_as_float(c0), __uint_as_float(c1),
                               __uint_as_float(c2), __uint_as_float(c3));
        *(float4*)&g_S[(size_t)(bm + (ty << 2) + i) * MM + bn + (tx << 2)] = v;
    }
}

// ---------------- Kernel 2: per-column top-l + hard scores  (R3-proven) -----
__global__ __launch_bounds__(32) void hard_kernel(const float* __restrict__ wb,
                                                  const int* __restrict__ lptr,
                                                  float* __restrict__ dst) {
    const int n    = blockIdx.x;
    const int lane = threadIdx.x;
    int l = lptr ? *lptr : 8;
    if (l < 1) l = 1;
    if (l > LMAX) l = LMAX;

    float v[16];
#pragma unroll
    for (int i = 0; i < 16; i++)
        v[i] = wb[(lane * 16 + i) * NN + n];

    float top[LMAX];
    for (int i = 0; i < l; i++) top[i] = -3.4e38f;
#pragma unroll
    for (int i = 0; i < 16; i++) {
        float x = v[i];
        if (x > top[l - 1]) {
            int j = l - 1;
            while (j > 0 && top[j - 1] < x) { top[j] = top[j - 1]; j--; }
            top[j] = x;
        }
    }

    int ptr = 0;
    float thr = -3.4e38f;
    for (int r = 0; r < l; r++) {
        float cand = (ptr < l) ? top[ptr] : -3.4e38f;
        float m = cand;
#pragma unroll
        for (int off = 16; off > 0; off >>= 1)
            m = fmaxf(m, __shfl_xor_sync(0xffffffffu, m, off));
        unsigned b = __ballot_sync(0xffffffffu, cand == m);
        int src = __ffs(b) - 1;
        if (lane == src) ptr++;
        thr = m;
    }

#pragma unroll
    for (int i = 0; i < 16; i++) {
        float sh = v[i] - thr + EPSV;
        sh = fminf(fmaxf(sh, -1.f), 1.f);
        float h = (sh + 1.f) * 0.5f;
        dst[(lane * 16 + i) * NN + n] = h;
    }
}

// ---------------- Kernel 3: warp-per-row softmax (R11-proven) ---------------
__global__ __launch_bounds__(256) void softmax_kernel(float* __restrict__ dst) {
    const int w    = threadIdx.x >> 5;
    const int lane = threadIdx.x & 31;
    const int k    = blockIdx.x * 8 + w;
    const float* row = g_S + (size_t)k * MM;

    float4 v[4];
#pragma unroll
    for (int j = 0; j < 4; j++)
        v[j] = __ldg((const float4*)(row + (lane << 2) + 128 * j));

    float mx = -3.4e38f;
#pragma unroll
    for (int j = 0; j < 4; j++)
        mx = fmaxf(mx, fmaxf(fmaxf(v[j].x, v[j].y), fmaxf(v[j].z, v[j].w)));
#pragma unroll
    for (int off = 16; off > 0; off >>= 1)
        mx = fmaxf(mx, __shfl_xor_sync(0xffffffffu, mx, off));

    float sum = 0.f;
#pragma unroll
    for (int j = 0; j < 4; j++) {
        v[j].x = __expf(v[j].x - mx);
        v[j].y = __expf(v[j].y - mx);
        v[j].z = __expf(v[j].z - mx);
        v[j].w = __expf(v[j].w - mx);
        sum += v[j].x + v[j].y + v[j].z + v[j].w;
    }
#pragma unroll
    for (int off = 16; off > 0; off >>= 1)
        sum += __shfl_xor_sync(0xffffffffu, sum, off);
    float inv = 1.f / sum;

    float* drow = dst + (size_t)k * MM;
#pragma unroll
    for (int j = 0; j < 4; j++) {
        float4 s = make_float4(v[j].x * inv + EPSV, v[j].y * inv + EPSV,
                               v[j].z * inv + EPSV, v[j].w * inv + EPSV);
        *(float4*)(drow + (lane << 2) + 128 * j) = s;
    }
}

// ---------------- Kernel 4: epilogue (R5-proven EXACT) ----------------------
// 16 threads per (k,m); each owns one float4 of n. Plain .wb stores.
__global__ __launch_bounds__(256) void epilogue_kernel(const float* __restrict__ x,
                                                       const float* __restrict__ soft,
                                                       const float* __restrict__ hard,
                                                       float* __restrict__ out,
                                                       float* __restrict__ mw) {
    const int idx = blockIdx.x * blockDim.x + threadIdx.x;  // 0 .. KK*MM*16-1
    const int n4  = idx & 15;
    const int km  = idx >> 4;       // 0 .. KK*MM-1
    const int m   = km & (MM - 1);

    float ss = __ldg(&soft[km]);
    float xv = __ldg(&x[km]);
    float4 h = __ldg((const float4*)(hard + m * NN + (n4 << 2)));

    float4 mw4 = make_float4(h.x * ss, h.y * ss, h.z * ss, h.w * ss);
    float4 o4  = make_float4(mw4.x * xv, mw4.y * xv, mw4.z * xv, mw4.w * xv);

    size_t base = (size_t)km * NN + (n4 << 2);
    *(float4*)&out[base] = o4;
    if (mw) *(float4*)&mw[base] = mw4;
}

// ---------------- launch: 4 sequential kernels (R11 structure) --------------
extern "C" void kernel_launch(void* const* d_in, const int* in_sizes, int n_in,
                              void* d_out, int out_size) {
    const float* x     = (const float*)d_in[0];
    const float* w_att = (const float*)d_in[1];
    const float* w_b   = (const float*)d_in[2];
    const int*   lptr  = (n_in > 3) ? (const int*)d_in[3] : nullptr;

    const long SZ_OUT  = (long)KK * MM * NN;
    const long SZ_HARD = (long)MM * NN;
    const long SZ_SOFT = (long)KK * MM;

    float* out_ptr = (float*)d_out;
    float* hard_dst;
    float* soft_dst;
    float* mw_ptr = nullptr;
    if ((long)out_size >= SZ_OUT + SZ_HARD + SZ_SOFT + SZ_OUT) {
        hard_dst = out_ptr + SZ_OUT;
        soft_dst = hard_dst + SZ_HARD;
        mw_ptr   = soft_dst + SZ_SOFT;
    } else {
        float* dummy;
        cudaGetSymbolAddress((void**)&dummy, g_hard);
        hard_dst = dummy;
        cudaGetSymbolAddress((void**)&dummy, g_soft);
        soft_dst = dummy;
    }

    hard_kernel<<<NN, 32>>>(w_b, lptr, hard_dst);

    dim3 ggrid(MM / BN, KK / BM);
    gemm_kernel<<<ggrid, 256>>>(x, w_att);

    softmax_kernel<<<KK / 8, 256>>>(soft_dst);

    epilogue_kernel<<<(KK * MM * 16) / 256, 256>>>(x, soft_dst, hard_dst,
                                                   out_ptr, mw_ptr);
}